// round 2
// baseline (speedup 1.0000x reference)
#include <cuda_runtime.h>

#define BB 16
#define NN 1024
#define DD 64
#define FIN 80
#define BN_EPS 1e-5f

// ---------------- scratch (device globals: no allocations allowed) ----------
__device__ float     g_h[BB*NN*DD];          // 4MB  node features
__device__ float     g_hW[BB*NN*DD];         // 4MB  relu(h @ Wl)
__device__ float     g_t1[BB*NN];
__device__ float     g_E1[BB*NN];
__device__ float2    g_te2[BB*NN];           // (t2, exp(t2))
__device__ unsigned  g_adjbits[BB*NN*(NN/32)];
__device__ float     g_Sall[BB*DD];          // per-batch column sums of hW

// ---------------- packed f32x2 helpers --------------------------------------
__device__ __forceinline__ unsigned long long pack2(float x, float y) {
    unsigned long long r;
    asm("mov.b64 %0, {%1, %2};" : "=l"(r) : "f"(x), "f"(y));
    return r;
}
__device__ __forceinline__ void unpack2(unsigned long long v, float &x, float &y) {
    asm("mov.b64 {%0, %1}, %2;" : "=f"(x), "=f"(y) : "l"(v));
}
__device__ __forceinline__ void ffma2(unsigned long long &d, unsigned long long a,
                                      unsigned long long b) {
    asm("fma.rn.f32x2 %0, %1, %2, %0;" : "+l"(d) : "l"(a), "l"(b));
}

// ---------------- kernel 1: pack adj into bitmask ---------------------------
__global__ void pack_adj_kernel(const int* __restrict__ adj) {
    int gt   = blockIdx.x * blockDim.x + threadIdx.x;
    int lane = gt & 31;
    int v = adj[gt];
    unsigned m = __ballot_sync(0xffffffffu, v > 0);
    if (lane == 0) g_adjbits[gt >> 5] = m;
}

// ---------------- kernel 2: h = relu(X @ W0) --------------------------------
__global__ void __launch_bounds__(128) input_proj_kernel(const float* __restrict__ X,
                                                         const float* __restrict__ W0) {
    __shared__ float  xs[64 * FIN];       // 64 rows of X (20KB)
    __shared__ float2 wp[FIN * 32];       // W0 packed (20KB)
    int tid = threadIdx.x;
    int rowbase = blockIdx.x * 64;

    const float4* xsrc = (const float4*)(X + (size_t)rowbase * FIN);
    float4* xdst = (float4*)xs;
    #pragma unroll
    for (int t = 0; t < 10; ++t) xdst[tid + t * 128] = xsrc[tid + t * 128];

    for (int idx = tid; idx < FIN * 32; idx += 128) {
        int k = idx >> 5, l = idx & 31;
        wp[idx] = make_float2(W0[k * 64 + l], W0[k * 64 + l + 32]);
    }
    __syncthreads();

    int w = tid >> 5, lane = tid & 31;
    for (int j = 0; j < 16; ++j) {
        int row = w * 16 + j;
        const float* xr = xs + row * FIN;
        float a0 = 0.f, a1 = 0.f;
        #pragma unroll
        for (int k = 0; k < FIN; k += 4) {
            float4 x4 = *(const float4*)(xr + k);
            float2 w0 = wp[(k + 0) * 32 + lane];
            float2 w1 = wp[(k + 1) * 32 + lane];
            float2 w2 = wp[(k + 2) * 32 + lane];
            float2 w3 = wp[(k + 3) * 32 + lane];
            a0 = fmaf(x4.x, w0.x, a0); a1 = fmaf(x4.x, w0.y, a1);
            a0 = fmaf(x4.y, w1.x, a0); a1 = fmaf(x4.y, w1.y, a1);
            a0 = fmaf(x4.z, w2.x, a0); a1 = fmaf(x4.z, w2.y, a1);
            a0 = fmaf(x4.w, w3.x, a0); a1 = fmaf(x4.w, w3.y, a1);
        }
        int gr = rowbase + row;
        g_h[gr * 64 + lane]      = fmaxf(a0, 0.f);
        g_h[gr * 64 + lane + 32] = fmaxf(a1, 0.f);
    }
}

// ---------------- zero S_all -------------------------------------------------
__global__ void zero_sall_kernel() {
    int idx = blockIdx.x * 128 + threadIdx.x;
    if (idx < BB * DD) g_Sall[idx] = 0.f;
}

// ------- kernel 3: hW = relu(h@Wl[i]); t1,t2,E1,(t2,E2); S_all (atomic) ------
__global__ void __launch_bounds__(128) hw_kernel(const float* __restrict__ Wl,
                                                 const float* __restrict__ a1l,
                                                 const float* __restrict__ a2l,
                                                 int li) {
    __shared__ float  hs[64 * 64];        // 16KB
    __shared__ float2 wp[64 * 32];        // 16KB
    int tid = threadIdx.x;
    int rowbase = blockIdx.x * 64;
    int b = rowbase >> 10;

    const float4* hsrc = (const float4*)(g_h + (size_t)rowbase * 64);
    float4* hdst = (float4*)hs;
    #pragma unroll
    for (int t = 0; t < 8; ++t) hdst[tid + t * 128] = hsrc[tid + t * 128];

    const float* W = Wl + li * 4096;
    for (int idx = tid; idx < 2048; idx += 128) {
        int k = idx >> 5, l = idx & 31;
        wp[idx] = make_float2(W[k * 64 + l], W[k * 64 + l + 32]);
    }
    __syncthreads();

    int w = tid >> 5, lane = tid & 31;
    float a1lo = a1l[li * 64 + lane], a1hi = a1l[li * 64 + lane + 32];
    float a2lo = a2l[li * 64 + lane], a2hi = a2l[li * 64 + lane + 32];
    float s0 = 0.f, s1 = 0.f;

    for (int j = 0; j < 16; ++j) {
        int row = w * 16 + j;
        const float* hr = hs + row * 64;
        float acc0 = 0.f, acc1 = 0.f;
        #pragma unroll
        for (int k = 0; k < 64; k += 4) {
            float4 h4 = *(const float4*)(hr + k);
            float2 w0 = wp[(k + 0) * 32 + lane];
            float2 w1 = wp[(k + 1) * 32 + lane];
            float2 w2 = wp[(k + 2) * 32 + lane];
            float2 w3 = wp[(k + 3) * 32 + lane];
            acc0 = fmaf(h4.x, w0.x, acc0); acc1 = fmaf(h4.x, w0.y, acc1);
            acc0 = fmaf(h4.y, w1.x, acc0); acc1 = fmaf(h4.y, w1.y, acc1);
            acc0 = fmaf(h4.z, w2.x, acc0); acc1 = fmaf(h4.z, w2.y, acc1);
            acc0 = fmaf(h4.w, w3.x, acc0); acc1 = fmaf(h4.w, w3.y, acc1);
        }
        acc0 = fmaxf(acc0, 0.f); acc1 = fmaxf(acc1, 0.f);
        int gr = rowbase + row;
        g_hW[gr * 64 + lane]      = acc0;
        g_hW[gr * 64 + lane + 32] = acc1;
        s0 += acc0; s1 += acc1;

        float p1 = fmaf(acc1, a1hi, acc0 * a1lo);
        float p2 = fmaf(acc1, a2hi, acc0 * a2lo);
        #pragma unroll
        for (int o = 16; o > 0; o >>= 1) {
            p1 += __shfl_down_sync(0xffffffffu, p1, o);
            p2 += __shfl_down_sync(0xffffffffu, p2, o);
        }
        if (lane == 0) {
            g_t1[gr]  = p1;
            g_E1[gr]  = __expf(p1);
            g_te2[gr] = make_float2(p2, __expf(p2));
        }
    }
    atomicAdd(&g_Sall[b * 64 + lane],      s0);
    atomicAdd(&g_Sall[b * 64 + lane + 32], s1);
}

// ---------------- kernel 4: fused masked attention + aggregate --------------
// one thread = one query row n.
// emb = (S_all + Σ_sel (E1·E2-1)·hW) / (N + Σ_sel (E1·E2-1))
__global__ void __launch_bounds__(128) attn_kernel(const float* __restrict__ root_list,
                                                   int rootLayer) {
    int b = blockIdx.x >> 3;
    int n = (blockIdx.x & 7) * 128 + threadIdx.x;
    int r = b * NN + n;

    float t1n = g_t1[r];
    float E1n = g_E1[r];

    unsigned long long acc[32];
    #pragma unroll
    for (int k = 0; k < 32; ++k) acc[k] = 0ull;
    float zacc = 0.f;

    __shared__ float4 hw_s[32 * 16];   // 32 rows x 64 floats (8KB)
    __shared__ float2 te_s[32];

    const float4* hwbase = (const float4*)(g_hW + (size_t)b * NN * DD);
    const float2* tebase = g_te2 + b * NN;
    const unsigned* awbase = g_adjbits + (size_t)r * 32;

    #pragma unroll 1
    for (int c = 0; c < 32; ++c) {
        __syncthreads();
        #pragma unroll
        for (int t = 0; t < 4; ++t)
            hw_s[threadIdx.x + t * 128] = hwbase[c * 512 + threadIdx.x + t * 128];
        if (threadIdx.x < 32) te_s[threadIdx.x] = tebase[c * 32 + threadIdx.x];
        unsigned aw = awbase[c];
        __syncthreads();

        #pragma unroll
        for (int j = 0; j < 32; ++j) {
            float2 te = te_s[j];
            bool p = ((aw >> j) & 1u) && (t1n + te.x > 0.f);
            float coef = p ? fmaf(E1n, te.y, -1.f) : 0.f;
            zacc += coef;
            unsigned long long c2 = pack2(coef, coef);
            const ulonglong2* hp = (const ulonglong2*)((const float*)hw_s + j * 64);
            #pragma unroll
            for (int k = 0; k < 16; ++k) {
                ulonglong2 h2 = hp[k];
                ffma2(acc[2 * k],     c2, h2.x);
                ffma2(acc[2 * k + 1], c2, h2.y);
            }
        }
    }

    float root = root_list[b * (4 * NN) + rootLayer * NN + n];
    if (root > 0.f) {
        float Z = (float)NN + zacc;
        float invZ = __fdividef(1.f, Z);
        const float4* sall = (const float4*)(g_Sall + b * 64);
        float4* hout = (float4*)(g_h + (size_t)r * 64);
        #pragma unroll
        for (int k = 0; k < 16; ++k) {
            float4 s = sall[k];
            float lx, ly, hx, hy;
            unpack2(acc[2 * k],     lx, ly);
            unpack2(acc[2 * k + 1], hx, hy);
            float4 o;
            o.x = (s.x + lx) * invZ;
            o.y = (s.y + ly) * invZ;
            o.z = (s.z + hx) * invZ;
            o.w = (s.w + hy) * invZ;
            hout[k] = o;
        }
    }
}

// ---------------- kernel 5: masked attention pool + BN-MLP head -------------
__global__ void __launch_bounds__(128) head_kernel(
    const float* __restrict__ root_list, const float* __restrict__ P,
    const float* __restrict__ pW1, const float* __restrict__ pb1,
    const float* __restrict__ g1,  const float* __restrict__ be1,
    const float* __restrict__ m1,  const float* __restrict__ v1,
    const float* __restrict__ pW2, const float* __restrict__ pb2,
    const float* __restrict__ g2,  const float* __restrict__ be2,
    const float* __restrict__ m2,  const float* __restrict__ v2,
    const float* __restrict__ pW3, const float* __restrict__ pb3,
    float* __restrict__ out) {

    __shared__ float  sh_w[NN];
    __shared__ float  sh_red[128];
    __shared__ float  sh_pool[64];
    __shared__ float  sh_x1[128];
    __shared__ float  sh_x2[64];
    __shared__ float4 sh_P[16];

    int b = blockIdx.x;
    int tid = threadIdx.x;
    if (tid < 16) sh_P[tid] = ((const float4*)P)[tid];
    __syncthreads();

    // phase 1: per-node scores -> weights
    float wsum = 0.f;
    for (int n = tid; n < NN; n += 128) {
        const float4* hr = (const float4*)(g_h + ((size_t)b * NN + n) * 64);
        float s = 0.f;
        #pragma unroll
        for (int k = 0; k < 16; ++k) {
            float4 h4 = hr[k]; float4 p4 = sh_P[k];
            s = fmaf(h4.x, p4.x, s);
            s = fmaf(h4.y, p4.y, s);
            s = fmaf(h4.z, p4.z, s);
            s = fmaf(h4.w, p4.w, s);
        }
        s = fmaxf(s, 0.f);
        float root = root_list[b * (4 * NN) + 1 * NN + n];
        float w = (root > 0.f) ? __expf(s) : 0.f;
        sh_w[n] = w;
        wsum += w;
    }
    sh_red[tid] = wsum;
    __syncthreads();
    for (int o = 64; o > 0; o >>= 1) {
        if (tid < o) sh_red[tid] += sh_red[tid + o];
        __syncthreads();
    }
    float invw = __fdividef(1.f, sh_red[0]);

    // phase 2: pooled vector (thread d owns output dim d)
    if (tid < 64) {
        float acc = 0.f;
        const float* hb = g_h + (size_t)b * NN * 64 + tid;
        for (int n = 0; n < NN; ++n) acc = fmaf(sh_w[n], hb[n * 64], acc);
        sh_pool[tid] = acc * invw;
    }
    __syncthreads();

    // MLP layer 1: 64 -> 128 with BN + relu
    {
        float acc = pb1[tid];
        #pragma unroll 8
        for (int k = 0; k < 64; ++k) acc = fmaf(sh_pool[k], pW1[k * 128 + tid], acc);
        float bnv = (acc - m1[tid]) * rsqrtf(v1[tid] + BN_EPS) * g1[tid] + be1[tid];
        sh_x1[tid] = fmaxf(bnv, 0.f);
    }
    __syncthreads();

    // MLP layer 2: 128 -> 64 with BN + relu
    if (tid < 64) {
        float acc = pb2[tid];
        #pragma unroll 8
        for (int k = 0; k < 128; ++k) acc = fmaf(sh_x1[k], pW2[k * 64 + tid], acc);
        float bnv = (acc - m2[tid]) * rsqrtf(v2[tid] + BN_EPS) * g2[tid] + be2[tid];
        sh_x2[tid] = fmaxf(bnv, 0.f);
    }
    __syncthreads();

    // MLP layer 3 + softmax(2)
    if (tid == 0) {
        float l0 = pb3[0], l1 = pb3[1];
        #pragma unroll 8
        for (int k = 0; k < 64; ++k) {
            l0 = fmaf(sh_x2[k], pW3[k * 2 + 0], l0);
            l1 = fmaf(sh_x2[k], pW3[k * 2 + 1], l1);
        }
        l0 = fmaxf(l0, 0.f); l1 = fmaxf(l1, 0.f);
        float mx = fmaxf(l0, l1);
        float e0 = __expf(l0 - mx), e1 = __expf(l1 - mx);
        float inv = __fdividef(1.f, e0 + e1);
        out[b * 2 + 0] = e0 * inv;
        out[b * 2 + 1] = e1 * inv;
    }
}

// ---------------- launch -----------------------------------------------------
extern "C" void kernel_launch(void* const* d_in, const int* in_sizes, int n_in,
                              void* d_out, int out_size) {
    const int*   adj       = (const int*)  d_in[0];
    const float* X         = (const float*)d_in[1];
    const float* root_list = (const float*)d_in[2];
    const float* W0        = (const float*)d_in[3];
    const float* Wl        = (const float*)d_in[4];
    const float* a1l       = (const float*)d_in[5];
    const float* a2l       = (const float*)d_in[6];
    const float* P         = (const float*)d_in[7];
    const float* pW1 = (const float*)d_in[8];  const float* pb1 = (const float*)d_in[9];
    const float* g1  = (const float*)d_in[10]; const float* be1 = (const float*)d_in[11];
    const float* m1  = (const float*)d_in[12]; const float* v1  = (const float*)d_in[13];
    const float* pW2 = (const float*)d_in[14]; const float* pb2 = (const float*)d_in[15];
    const float* g2  = (const float*)d_in[16]; const float* be2 = (const float*)d_in[17];
    const float* m2  = (const float*)d_in[18]; const float* v2  = (const float*)d_in[19];
    const float* pW3 = (const float*)d_in[20]; const float* pb3 = (const float*)d_in[21];
    float* out = (float*)d_out;

    pack_adj_kernel<<<BB * NN * NN / 256, 256>>>(adj);
    input_proj_kernel<<<BB * NN / 64, 128>>>(X, W0);

    for (int li = 0; li < 3; ++li) {
        zero_sall_kernel<<<8, 128>>>();
        hw_kernel<<<BB * NN / 64, 128>>>(Wl, a1l, a2l, li);
        attn_kernel<<<BB * 8, 128>>>(root_list, 3 - li);
    }

    head_kernel<<<BB, 128>>>(root_list, P,
                             pW1, pb1, g1, be1, m1, v1,
                             pW2, pb2, g2, be2, m2, v2,
                             pW3, pb3, out);
}